// round 16
// baseline (speedup 1.0000x reference)
#include <cuda_runtime.h>
#include <cuda_fp16.h>
#include <cstdint>

// ============================================================================
// GGRUCell on GB300 — HMMA fp16 single-term GEMMs.
// R16 = R15 epi-streaming + R10 occupancy: CTA 128x64, warp tile 32x32,
// 3 CTAs/SM (24 warps). The R14/R15 ledger showed the GEMMs are DRAM-traffic
// bound at ~1-1.6 TB/s ACHIEVED (vs 7 TB/s in the streaming prep kernel):
// the fix is more concurrent cp.async streams, i.e. occupancy.
//
//   R   = sigmoid(prev @ Wr + inp[:,2H:]) * inp[:,:H]
//   out = mask * (tanh(R @ U + inp[:,:H]) + 1) + prev   (update gate cancels)
// ============================================================================

#define HDIM   1024
#define BATCH  16384

static constexpr int M_TILE = 128;
static constexpr int N_TILE = 64;
static constexpr int KT     = 32;            // K-chunk
static constexpr int NCH    = HDIM / KT;     // 32 chunks
static constexpr int NC     = HDIM / 32;     // 32 k32-granules (B frag layout)
static constexpr int SA     = 40;            // padded A smem row stride (fp16)

static constexpr int A_BYTES    = 128 * SA * 2;           // 10240
static constexpr int B_BYTES    = 8 * 512;                // 4096
static constexpr int STG_BYTES  = A_BYTES + B_BYTES;      // 14336
static constexpr int OFF_B      = A_BYTES;
static constexpr int EPI_OFF    = 2 * STG_BYTES;          // 28672
static constexpr int PITCH_S    = 136;  // converted fp16 planes (64 cols + pad)
static constexpr int PITCH_P    = 144;  // prev16 plane (cp.async 16B align)
static constexpr int PLANE_S    = 128 * PITCH_S;          // 17408
static constexpr int PLANE_P    = 128 * PITCH_P;          // 18432
// FIRST : e0=si16(PLANE_S) e1=gi16(PLANE_S) staging 2x2048  -> 67584
// !FIRST: e0=si16(PLANE_S) e1=prev16(PLANE_P) staging 2x1024 -> 66560
static constexpr int SMEM_BYTES = EPI_OFF + 2 * PLANE_S + 2 * 2048;  // 67584

// --------------------------------------------------------------------------
__device__ __forceinline__ uint32_t smem_to_u32(const void* p) {
    uint32_t a;
    asm("{ .reg .u64 t; cvta.to.shared.u64 t, %1; cvt.u32.u64 %0, t; }" : "=r"(a) : "l"(p));
    return a;
}
#define CP_ASYNC16(s, g) \
    asm volatile("cp.async.cg.shared.global [%0], [%1], 16;" :: "r"(s), "l"(g) : "memory")
#define CP_COMMIT() asm volatile("cp.async.commit_group;" ::: "memory")
#define CP_WAIT1()  asm volatile("cp.async.wait_group 1;" ::: "memory")
#define CP_WAIT0()  asm volatile("cp.async.wait_group 0;" ::: "memory")

#define LDSM_X4(r0, r1, r2, r3, addr) \
    asm volatile("ldmatrix.sync.aligned.m8n8.x4.shared.b16 {%0,%1,%2,%3}, [%4];" \
                 : "=r"(r0), "=r"(r1), "=r"(r2), "=r"(r3) : "r"(addr))

#define LDS128(v, addr) \
    asm volatile("ld.shared.v4.u32 {%0,%1,%2,%3}, [%4];" \
                 : "=r"((v).x), "=r"((v).y), "=r"((v).z), "=r"((v).w) : "r"(addr))

#define LDSF4(v, addr) \
    asm volatile("ld.shared.v4.f32 {%0,%1,%2,%3}, [%4];" \
                 : "=f"((v).x), "=f"((v).y), "=f"((v).z), "=f"((v).w) : "r"(addr))

#define STS8(addr, a, b) \
    asm volatile("st.shared.v2.b32 [%0], {%1, %2};" :: "r"(addr), "r"(a), "r"(b) : "memory")

#define LDSH2F(f2, addr) do { \
    uint32_t _u; \
    asm volatile("ld.shared.b32 %0, [%1];" : "=r"(_u) : "r"(addr)); \
    __half2 _h = *reinterpret_cast<__half2*>(&_u); \
    (f2) = __half22float2(_h); \
} while (0)

#define MMA_F16_2(d, a, b0, b1) \
    asm volatile("mma.sync.aligned.m16n8k16.row.col.f32.f16.f16.f32 " \
                 "{%0,%1,%2,%3}, {%4,%5,%6,%7}, {%8,%9}, {%0,%1,%2,%3};" \
                 : "+f"((d)[0]), "+f"((d)[1]), "+f"((d)[2]), "+f"((d)[3]) \
                 : "r"((a)[0]), "r"((a)[1]), "r"((a)[2]), "r"((a)[3]), \
                   "r"(b0), "r"(b1))

// --------------------------------------------------------------------------
// Scratch (no cudaMalloc allowed)
// --------------------------------------------------------------------------
__device__ uint4 g_W1f[(HDIM / 8) * NC * 32];   // Wr fragment-linear fp16
__device__ uint4 g_W2f[(HDIM / 8) * NC * 32];   // U  fragment-linear fp16
__device__ __half g_Ph[(size_t)BATCH * HDIM];   // prev  fp16
__device__ __half g_Rh[(size_t)BATCH * HDIM];   // R = reset*state fp16

__device__ __forceinline__ uint32_t pack_h2(__half a, __half b) {
    __half2 t; t.x = a; t.y = b;
    return *reinterpret_cast<uint32_t*>(&t);
}

// --------------------------------------------------------------------------
__global__ void prep_kernel(const float* __restrict__ prev) {
    const size_t i = ((size_t)blockIdx.x * 256 + threadIdx.x) * 4;
    const float4 pv = *reinterpret_cast<const float4*>(&prev[i]);
    *reinterpret_cast<uint2*>(&g_Ph[i]) = make_uint2(
        pack_h2(__float2half(pv.x), __float2half(pv.y)),
        pack_h2(__float2half(pv.z), __float2half(pv.w)));
}

// --------------------------------------------------------------------------
__global__ void wtrans_frag(const float* __restrict__ W, int ld, int off, int which) {
    const int t    = blockIdx.x * 256 + threadIdx.x;
    const int lane = t & 31;
    const int k32  = (t >> 5) & (NC - 1);
    const int n8   = t >> 10;
    const int n    = n8 * 8 + (lane >> 2);
    const int kb   = k32 * 32 + 2 * (lane & 3);
    uint32_t h[4];
#pragma unroll
    for (int w = 0; w < 4; w++) {
        const int k = kb + 8 * w;
        const float v0 = W[(size_t)k * ld + off + n];
        const float v1 = W[(size_t)(k + 1) * ld + off + n];
        h[w] = pack_h2(__float2half(v0), __float2half(v1));
    }
    uint4* F = which ? g_W2f : g_W1f;
    F[t] = make_uint4(h[0], h[1], h[2], h[3]);
}

// --------------------------------------------------------------------------
// GEMM: CTA 128x64, 8 warps (4M x 2N), warp tile 32x32, K-chunk 32,
// 2-stage cp.async (refill after drain), epi slices staged+converted in-loop.
// 3 CTAs/SM.
// --------------------------------------------------------------------------
template <bool FIRST>
__global__ void __launch_bounds__(256, 3)
gemm_kernel(const float* __restrict__ inp, const float* __restrict__ mask,
            float* __restrict__ out) {
    extern __shared__ char smem_raw[];
    const uint32_t sb = smem_to_u32(smem_raw);

    const int tid   = threadIdx.x;
    const int wid   = tid >> 5;
    const int lane  = tid & 31;
    const int warpM = wid >> 1;       // 4 warps over M (32 rows each)
    const int warpN = wid & 1;        // 2 warps over N (32 cols each)
    const int m0 = blockIdx.x * M_TILE;
    const int n0 = blockIdx.y * N_TILE;

    const __half* AHg = FIRST ? g_Ph : g_Rh;
    const uint4* __restrict__ BF = FIRST ? g_W1f : g_W2f;
    const int nb0 = n0 >> 3;          // 8 n8-tiles per CTA

    const uint32_t e0  = sb + EPI_OFF;                           // si16
    const uint32_t e1  = e0 + PLANE_S;                           // gi16 / prev16
    const uint32_t stg = FIRST ? (e1 + PLANE_S) : (e1 + PLANE_P);
    const uint32_t SSZ = FIRST ? 2048u : 1024u;

    auto issue_chunk = [&](int kc, int stage) {
        const uint32_t s0 = sb + stage * STG_BYTES;
        // A: 128 rows x 4 granules = 512 granules, 2/thread
#pragma unroll
        for (int i = 0; i < 2; i++) {
            const int g   = tid + i * 256;
            const int row = g >> 2;
            const int ce  = (g & 3) * 8;
            const size_t gA = (size_t)(m0 + row) * HDIM + kc * KT + ce;
            const uint32_t so = (uint32_t)(row * SA + ce) * 2;
            CP_ASYNC16(s0 + so, AHg + gA);
        }
        // B: 8 n8-tiles x 32 lanes = 256 granules, 1/thread
        {
            const int t8 = tid >> 5;
            const int ln = tid & 31;
            const int idx = ((nb0 + t8) * NC + kc) * 32 + ln;
            CP_ASYNC16(s0 + OFF_B + (uint32_t)tid * 16, &BF[idx]);
        }
    };

    // slice s (0..31): rows 4s..4s+3 of the epi tiles (64 cols).
    auto issue_slice = [&](int s) {
        if (FIRST) {
            // si + gi fp32: 2 planes x 4 rows x 16 granules = 128 granules
            if (tid < 128) {
                const int p  = tid >> 6;
                const int r  = (tid >> 4) & 3;
                const int cg = tid & 15;
                const float* src = inp + (size_t)(m0 + 4 * s + r) * 3072
                                   + (p ? 2048 : 0) + n0 + cg * 4;
                const uint32_t dst = stg + (s & 1) * SSZ + p * 1024 + r * 256 + cg * 16;
                CP_ASYNC16(dst, src);
            }
        } else {
            if (tid < 64) {       // si fp32: 64 granules
                const int r  = tid >> 4;
                const int cg = tid & 15;
                const float* src = inp + (size_t)(m0 + 4 * s + r) * 3072 + n0 + cg * 4;
                const uint32_t dst = stg + (s & 1) * SSZ + r * 256 + cg * 16;
                CP_ASYNC16(dst, src);
            } else if (tid < 96) {  // prev16 direct: 32 granules into e1
                const int h  = tid - 64;
                const int r  = h >> 3;
                const int c8 = h & 7;
                const __half* src = g_Ph + (size_t)(m0 + 4 * s + r) * HDIM + n0 + c8 * 8;
                const uint32_t dst = e1 + (uint32_t)(4 * s + r) * PITCH_P + c8 * 16;
                CP_ASYNC16(dst, src);
            }
        }
    };

    auto convert_slice = [&](int s) {
        if (FIRST) {
            if (tid < 128) {
                const int p  = tid >> 6;
                const int r  = (tid >> 4) & 3;
                const int cg = tid & 15;
                float4 v;
                LDSF4(v, stg + (s & 1) * SSZ + p * 1024 + r * 256 + cg * 16);
                const uint32_t d = (p ? e1 : e0) + (uint32_t)(4 * s + r) * PITCH_S + cg * 8;
                STS8(d, pack_h2(__float2half(v.x), __float2half(v.y)),
                        pack_h2(__float2half(v.z), __float2half(v.w)));
            }
        } else {
            if (tid < 64) {
                const int r  = tid >> 4;
                const int cg = tid & 15;
                float4 v;
                LDSF4(v, stg + (s & 1) * SSZ + r * 256 + cg * 16);
                const uint32_t d = e0 + (uint32_t)(4 * s + r) * PITCH_S + cg * 8;
                STS8(d, pack_h2(__float2half(v.x), __float2half(v.y)),
                        pack_h2(__float2half(v.z), __float2half(v.w)));
            }
        }
    };

    float acc[2][4][4];
#pragma unroll
    for (int i = 0; i < 2; i++)
#pragma unroll
        for (int j = 0; j < 4; j++)
#pragma unroll
            for (int k = 0; k < 4; k++) acc[i][j][k] = 0.f;

    issue_chunk(0, 0); issue_slice(0); CP_COMMIT();
    issue_chunk(1, 1); issue_slice(1); CP_COMMIT();

    for (int c = 0; c < NCH; c++) {
        CP_WAIT1();                 // group c complete
        __syncthreads();

        const uint32_t s0 = sb + (c & 1) * STG_BYTES;
        const uint32_t sB = s0 + OFF_B + (uint32_t)warpN * 4 * 512 + lane * 16;

        uint4 B4[4];
#pragma unroll
        for (int ni = 0; ni < 4; ni++) LDS128(B4[ni], sB + ni * 512);

        convert_slice(c);

#pragma unroll
        for (int kb2 = 0; kb2 < 2; kb2++) {
            const int kcol = kb2 * 16 + ((lane >> 4) << 3);
            uint32_t a0[4], a1[4];
            {
                const int r0 = warpM * 32 + (lane & 15);
                const int r1 = warpM * 32 + 16 + (lane & 15);
                const uint32_t o0 = (uint32_t)(r0 * SA + kcol) * 2;
                const uint32_t o1 = (uint32_t)(r1 * SA + kcol) * 2;
                LDSM_X4(a0[0], a0[1], a0[2], a0[3], s0 + o0);
                LDSM_X4(a1[0], a1[1], a1[2], a1[3], s0 + o1);
            }
#pragma unroll
            for (int ni = 0; ni < 4; ni++) {
                const uint32_t b0 = kb2 ? B4[ni].z : B4[ni].x;
                const uint32_t b1 = kb2 ? B4[ni].w : B4[ni].y;
                MMA_F16_2(acc[0][ni], a0, b0, b1);
                MMA_F16_2(acc[1][ni], a1, b0, b1);
            }
        }
        __syncthreads();            // stage c&1 + staging c&1 drained

        if (c + 2 < NCH) {
            issue_chunk(c + 2, (c + 2) & 1);
            issue_slice(c + 2);
        }
        CP_COMMIT();
    }

    CP_WAIT0();
    __syncthreads();

    // ---- epilogue (operands in smem) ----
#pragma unroll
    for (int mi = 0; mi < 2; mi++) {
#pragma unroll
        for (int h = 0; h < 2; h++) {
            const int row = warpM * 32 + mi * 16 + h * 8 + (lane >> 2);
            const int b   = m0 + row;
            float mval = 0.f;
            if (!FIRST) mval = __ldg(&mask[b]);
#pragma unroll
            for (int ni = 0; ni < 4; ni++) {
                const int col = warpN * 32 + ni * 8 + (lane & 3) * 2;
                const float v0 = acc[mi][ni][2 * h];
                const float v1 = acc[mi][ni][2 * h + 1];
                float2 sif; LDSH2F(sif, e0 + (uint32_t)(row * PITCH_S + col * 2));
                if (FIRST) {
                    float2 gif; LDSH2F(gif, e1 + (uint32_t)(row * PITCH_S + col * 2));
                    const float r0 = sif.x / (1.f + __expf(-(v0 + gif.x)));
                    const float r1 = sif.y / (1.f + __expf(-(v1 + gif.y)));
                    *reinterpret_cast<uint32_t*>(&g_Rh[(size_t)b * HDIM + n0 + col]) =
                        pack_h2(__float2half(r0), __float2half(r1));
                } else {
                    float2 pvf; LDSH2F(pvf, e1 + (uint32_t)(row * PITCH_P + col * 2));
                    float2 o;
                    o.x = mval * (tanhf(v0 + sif.x) + 1.f) + pvf.x;
                    o.y = mval * (tanhf(v1 + sif.y) + 1.f) + pvf.y;
                    *reinterpret_cast<float2*>(&out[(size_t)b * HDIM + n0 + col]) = o;
                }
            }
        }
    }
}

// --------------------------------------------------------------------------
extern "C" void kernel_launch(void* const* d_in, const int* in_sizes, int n_in,
                              void* d_out, int out_size) {
    const float* inp  = (const float*)d_in[0];   // (B, 3H)
    const float* prev = (const float*)d_in[1];   // (B, H)
    const float* mask = (const float*)d_in[2];   // (B,)
    const float* Wur  = (const float*)d_in[3];   // (H, 2H)
    const float* U    = (const float*)d_in[4];   // (H, H)
    float* out = (float*)d_out;

    cudaFuncSetAttribute(gemm_kernel<true>,
                         cudaFuncAttributeMaxDynamicSharedMemorySize, SMEM_BYTES);
    cudaFuncSetAttribute(gemm_kernel<false>,
                         cudaFuncAttributeMaxDynamicSharedMemorySize, SMEM_BYTES);

    prep_kernel<<<(BATCH * HDIM) / (256 * 4), 256>>>(prev);
    const int frag_slots = (HDIM / 8) * NC * 32;           // 131072
    wtrans_frag<<<frag_slots / 256, 256>>>(Wur, 2 * HDIM, HDIM, 0);  // Wr
    wtrans_frag<<<frag_slots / 256, 256>>>(U, HDIM, 0, 1);

    dim3 grid(BATCH / M_TILE, HDIM / N_TILE);
    gemm_kernel<true><<<grid, 256, SMEM_BYTES>>>(inp, mask, out);
    gemm_kernel<false><<<grid, 256, SMEM_BYTES>>>(inp, mask, out);
}